// round 11
// baseline (speedup 1.0000x reference)
// ============================================================================
// R10: resubmission of the chunk-parity dual-group flash attention kernel.
//
// Theory (unchanged from R8): the R6 best (254 us; attn ~211 us) is bound by
// SMEM crossbar traffic + serialization: 16x32 warp tiles => 232 KB/chunk of
// LDSM+STS traffic (~1900 cyc floor at 128 B/cyc) on top of HMMA. This kernel
// gets 32x32 warp tiles (128 KB/chunk LDSM => ~1310 cyc floor) AND 8
// warps/SMSP of latency hiding simultaneously via two chunk-parity groups:
// 1024 threads = 2 groups x 16 warps, interleaved across SMSPs (parity = bit2
// of wid). Group p handles chunks c == p (mod 2) with its own P buffer,
// double-buffered Hs, and its own named barrier (bar.sync p+1, 512). Each
// group runs a simple serialized produce -> bar -> MMA -> bar loop; the other
// group's warps fill the SMSP issue/latency gaps, so no intra-group pipelining
// is needed. At the end group 1 stores partial accumulators to SMEM (padded
// pitch) and group 0 combines + does the sigmoid epilogue; rowsums add.
//
// Prediction: total 254 -> ~195-215 us, rel_err ~4.4e-5. If >=240 us, suspect
// register pressure/spills at 1024 threads (check regs in ncu next round).
// ============================================================================
#include <cuda_runtime.h>
#include <cuda_bf16.h>
#include <math_constants.h>
#include <cstdint>

#define NNODES 8192
#define FIN    512
#define FOUT   256
#define NEG_SLOPE 0.2f

#define BM 64
#define BK 64
#define NCHUNK (NNODES / BK)     // 128
#define ATTN_THREADS 1024        // 2 parity groups x 16 warps

// ---------------- device scratch ----------------
__device__ float         g_H [NNODES * FOUT];
__device__ __nv_bfloat16 g_HT[FOUT * NNODES];
__device__ float         g_s [NNODES];
__device__ float         g_t [NNODES];

// ---------------- helpers (base PTX, sm_80-compatible) ----------------
static __device__ __forceinline__ uint32_t smem_u32(const void* p) {
    uint32_t a;
    asm("{ .reg .u64 t; cvta.to.shared.u64 t, %1; cvt.u32.u64 %0, t; }" : "=r"(a) : "l"(p));
    return a;
}
static __device__ __forceinline__ void cp_async16(uint32_t dst, const void* src) {
    asm volatile("cp.async.cg.shared.global [%0], [%1], 16;" :: "r"(dst), "l"(src));
}
static __device__ __forceinline__ void cp_commit() {
    asm volatile("cp.async.commit_group;" ::: "memory");
}
static __device__ __forceinline__ void cp_wait_all() {
    asm volatile("cp.async.wait_group 0;" ::: "memory");
}
static __device__ __forceinline__ void cp_wait_1() {
    asm volatile("cp.async.wait_group 1;" ::: "memory");
}
static __device__ __forceinline__ void bar_named(int id, int cnt) {
    asm volatile("bar.sync %0, %1;" :: "r"(id), "r"(cnt) : "memory");
}
static __device__ __forceinline__ void ldm_x4(uint32_t& r0, uint32_t& r1,
                                              uint32_t& r2, uint32_t& r3, uint32_t addr) {
    asm volatile("ldmatrix.sync.aligned.m8n8.x4.shared.b16 {%0, %1, %2, %3}, [%4];"
                 : "=r"(r0), "=r"(r1), "=r"(r2), "=r"(r3) : "r"(addr));
}
static __device__ __forceinline__ void mma_16816(float* d, const uint32_t* a, const uint32_t* b) {
    asm volatile(
        "mma.sync.aligned.m16n8k16.row.col.f32.bf16.bf16.f32 "
        "{%0, %1, %2, %3}, {%4, %5, %6, %7}, {%8, %9}, {%0, %1, %2, %3};"
        : "+f"(d[0]), "+f"(d[1]), "+f"(d[2]), "+f"(d[3])
        : "r"(a[0]), "r"(a[1]), "r"(a[2]), "r"(a[3]), "r"(b[0]), "r"(b[1]));
}
static __device__ __forceinline__ void mma_tf32(float* d, const uint32_t* a, const uint32_t* b) {
    asm volatile(
        "mma.sync.aligned.m16n8k8.row.col.f32.tf32.tf32.f32 "
        "{%0, %1, %2, %3}, {%4, %5, %6, %7}, {%8, %9}, {%0, %1, %2, %3};"
        : "+f"(d[0]), "+f"(d[1]), "+f"(d[2]), "+f"(d[3])
        : "r"(a[0]), "r"(a[1]), "r"(a[2]), "r"(a[3]), "r"(b[0]), "r"(b[1]));
}
static __device__ __forceinline__ uint32_t f2tf32(float v) {
    uint32_t r;
    asm("cvt.rna.tf32.f32 %0, %1;" : "=r"(r) : "f"(v));
    return r;
}
static __device__ __forceinline__ uint32_t sw128(uint32_t b) { return b ^ ((b >> 3) & 0x70); }

// ---------------- Kernel 1: H = X @ W^T via tf32 mma ----------------
#define GPITCH 36
#define XS_OFF0 0u
#define XS_OFF1 18432u
#define WS_OFF0 36864u
#define WS_OFF1 46080u
#define GEMM_SMEM 55296

__global__ void __launch_bounds__(256)
gemm_H_tf32_kernel(const float* __restrict__ X, const float* __restrict__ W) {
    extern __shared__ char gsm[];
    const uint32_t base = smem_u32(gsm);
    float* sm = (float*)gsm;

    const int tid = threadIdx.x;
    const int lane = tid & 31;
    const int wid = tid >> 5;
    const int wm = (wid & 3) * 32;
    const int wn = (wid >> 2) * 32;
    const int row0 = blockIdx.x * 128;
    const int col0 = blockIdx.y * 64;

    float acc[2][4][4];
#pragma unroll
    for (int mt = 0; mt < 2; mt++)
#pragma unroll
        for (int nt = 0; nt < 4; nt++)
#pragma unroll
            for (int e = 0; e < 4; e++) acc[mt][nt][e] = 0.f;

#pragma unroll
    for (int q = 0; q < 4; q++) {
        int id = tid + q * 256;
        int r = id >> 3, kq = id & 7;
        cp_async16(base + XS_OFF0 + (uint32_t)(r * GPITCH + kq * 4) * 4u,
                   X + (size_t)(row0 + r) * FIN + kq * 4);
    }
#pragma unroll
    for (int q = 0; q < 2; q++) {
        int id = tid + q * 256;
        int r = id >> 3, kq = id & 7;
        cp_async16(base + WS_OFF0 + (uint32_t)(r * GPITCH + kq * 4) * 4u,
                   W + (size_t)(col0 + r) * FIN + kq * 4);
    }
    cp_commit();

    const int a_r = lane >> 2;
    const int a_k = lane & 3;

#pragma unroll 1
    for (int kb = 0; kb < FIN / 32; kb++) {
        const int buf = kb & 1;
        const uint32_t xs = buf ? XS_OFF1 : XS_OFF0;
        const uint32_t ws = buf ? WS_OFF1 : WS_OFF0;
        cp_wait_all();
        __syncthreads();

        if (kb + 1 < FIN / 32) {
            const uint32_t xsn = buf ? XS_OFF0 : XS_OFF1;
            const uint32_t wsn = buf ? WS_OFF0 : WS_OFF1;
            const int k0n = (kb + 1) * 32;
#pragma unroll
            for (int q = 0; q < 4; q++) {
                int id = tid + q * 256;
                int r = id >> 3, kq = id & 7;
                cp_async16(base + xsn + (uint32_t)(r * GPITCH + kq * 4) * 4u,
                           X + (size_t)(row0 + r) * FIN + k0n + kq * 4);
            }
#pragma unroll
            for (int q = 0; q < 2; q++) {
                int id = tid + q * 256;
                int r = id >> 3, kq = id & 7;
                cp_async16(base + wsn + (uint32_t)(r * GPITCH + kq * 4) * 4u,
                           W + (size_t)(col0 + r) * FIN + k0n + kq * 4);
            }
            cp_commit();
        }

        const float* Xs = (const float*)((const char*)sm + xs);
        const float* Ws = (const float*)((const char*)sm + ws);
#pragma unroll
        for (int kk = 0; kk < 32; kk += 8) {
            uint32_t a[2][4];
#pragma unroll
            for (int mt = 0; mt < 2; mt++) {
                const int m = wm + mt * 16 + a_r;
                a[mt][0] = f2tf32(Xs[m * GPITCH + kk + a_k]);
                a[mt][1] = f2tf32(Xs[(m + 8) * GPITCH + kk + a_k]);
                a[mt][2] = f2tf32(Xs[m * GPITCH + kk + a_k + 4]);
                a[mt][3] = f2tf32(Xs[(m + 8) * GPITCH + kk + a_k + 4]);
            }
            uint32_t b[4][2];
#pragma unroll
            for (int nt = 0; nt < 4; nt++) {
                const int n = wn + nt * 8 + a_r;
                b[nt][0] = f2tf32(Ws[n * GPITCH + kk + a_k]);
                b[nt][1] = f2tf32(Ws[n * GPITCH + kk + a_k + 4]);
            }
#pragma unroll
            for (int mt = 0; mt < 2; mt++)
#pragma unroll
                for (int nt = 0; nt < 4; nt++)
                    mma_tf32(acc[mt][nt], a[mt], b[nt]);
        }
    }

#pragma unroll
    for (int mt = 0; mt < 2; mt++) {
#pragma unroll
        for (int nt = 0; nt < 4; nt++) {
#pragma unroll
            for (int half = 0; half < 2; half++) {
                const int row = row0 + wm + mt * 16 + (lane >> 2) + half * 8;
                const int col = col0 + wn + nt * 8 + (lane & 3) * 2;
                float v0 = acc[mt][nt][2 * half];
                float v1 = acc[mt][nt][2 * half + 1];
                *reinterpret_cast<float2*>(g_H + (size_t)row * FOUT + col) = make_float2(v0, v1);
                g_HT[(size_t)col * NNODES + row]       = __float2bfloat16(v0);
                g_HT[(size_t)(col + 1) * NNODES + row] = __float2bfloat16(v1);
            }
        }
    }
}

// ---------------- Kernel 2: s = H a_l, t = H a_r ----------------
__global__ void st_kernel(const float* __restrict__ attn_w) {
    const int lane = threadIdx.x & 31;
    const int warp = threadIdx.x >> 5;
    const int row = blockIdx.x * 8 + warp;
    float s = 0.f, t = 0.f;
#pragma unroll
    for (int o = lane; o < FOUT; o += 32) {
        float h = g_H[(size_t)row * FOUT + o];
        s += h * attn_w[o];
        t += h * attn_w[FOUT + o];
    }
#pragma unroll
    for (int off = 16; off; off >>= 1) {
        s += __shfl_down_sync(0xffffffffu, s, off);
        t += __shfl_down_sync(0xffffffffu, t, off);
    }
    if (lane == 0) { g_s[row] = s; g_t[row] = t; }
}

// ---------------- Kernel 3: chunk-parity dual-group flash attention ----------------
#define P_OFF(p)    ((uint32_t)(p) * 8192u)
#define HS_OFF(p,b) (16384u + ((uint32_t)((p) * 2 + (b))) * 32768u)
#define RS_OFF      147456u
#define ACC_OFF     16384u
#define ACC_PITCH   264
#define SMEM_DYN    149504

__global__ void __launch_bounds__(ATTN_THREADS, 1)
attn_mma_kernel(const float* __restrict__ M, float* __restrict__ out) {
    extern __shared__ char dsm[];
    const uint32_t raw = smem_u32(dsm);
    const uint32_t base = (raw + 1023u) & ~1023u;
    char* al = dsm + (base - raw);

    const int tid  = threadIdx.x;
    const int lane = tid & 31;
    const int wid  = tid >> 5;
    const int row0 = blockIdx.x * BM;

    // parity groups interleaved across SMSPs: parity = bit2 of wid
    const int par  = (wid >> 2) & 1;
    const int gw   = (wid & 3) | ((wid >> 3) << 2);   // 0..15 group-local warp
    const int gtid = gw * 32 + lane;                   // 0..511

    // producer mapping within group: row = gtid/8, 8 cols at (gtid%8)*8
    const int pr_r   = gtid >> 3;
    const int pr_seg = gtid & 7;
    const float si = g_s[row0 + pr_r];
    const float* Mrow = M + (size_t)(row0 + pr_r) * NNODES + pr_seg * 8;

    // warp MMA tile 32x32: 2 m-groups x 8 n-groups
    const int mrow0 = (gw & 1) * 32;
    const int ncol0 = (gw >> 1) * 32;

    float acc[2][4][4];
#pragma unroll
    for (int mt = 0; mt < 2; mt++)
#pragma unroll
        for (int nt = 0; nt < 4; nt++)
#pragma unroll
            for (int e = 0; e < 4; e++) acc[mt][nt][e] = 0.f;

    float rs_reg = 0.f;
    const uint32_t ps_off = P_OFF(par);
    const int barid = par + 1;

    // ---- prologue: Hs(par) -> HS(par,0), Hs(par+2) -> HS(par,1) ----
#pragma unroll
    for (int b = 0; b < 2; b++) {
        const int gc = par + 2 * b;
#pragma unroll
        for (int q = 0; q < 4; q++) {
            int id = gtid + q * 512;               // 0..2047 uint4
            int n = id >> 3, kq = id & 7;
            cp_async16(base + HS_OFF(par, b) + sw128((uint32_t)n * 128u + (uint32_t)kq * 16u),
                       g_HT + (size_t)n * NNODES + gc * BK + kq * 8);
        }
        cp_commit();
    }

    // M(par) -> regs
    float4 mcur0 = *reinterpret_cast<const float4*>(Mrow + par * BK);
    float4 mcur1 = *reinterpret_cast<const float4*>(Mrow + par * BK + 4);

#pragma unroll 1
    for (int i = 0; i < NCHUNK / 2; ++i) {
        const int gc = 2 * i + par;
        const uint32_t hs_off = HS_OFF(par, i & 1);

        // 1. produce P(gc) into P(par) (prior MMA of this group done -> safe)
        {
            const float* tp = g_t + gc * BK + pr_seg * 8;
            const float4 t40 = *reinterpret_cast<const float4*>(tp);
            const float4 t41 = *reinterpret_cast<const float4*>(tp + 4);
            float pr[8];
#pragma unroll
            for (int e = 0; e < 4; e++) {
                float m = (&mcur0.x)[e];
                float v = si + (&t40.x)[e];
                float lr = fmaxf(v, NEG_SLOPE * v);
                float pv = (m > 0.f) ? __expf(m * lr) : 0.f;
                pr[e] = __bfloat162float(__float2bfloat16(pv));
            }
#pragma unroll
            for (int e = 0; e < 4; e++) {
                float m = (&mcur1.x)[e];
                float v = si + (&t41.x)[e];
                float lr = fmaxf(v, NEG_SLOPE * v);
                float pv = (m > 0.f) ? __expf(m * lr) : 0.f;
                pr[4 + e] = __bfloat162float(__float2bfloat16(pv));
            }
            uint4 packed;
            __nv_bfloat162 p01 = __floats2bfloat162_rn(pr[0], pr[1]);
            __nv_bfloat162 p23 = __floats2bfloat162_rn(pr[2], pr[3]);
            __nv_bfloat162 p45 = __floats2bfloat162_rn(pr[4], pr[5]);
            __nv_bfloat162 p67 = __floats2bfloat162_rn(pr[6], pr[7]);
            packed.x = *reinterpret_cast<uint32_t*>(&p01);
            packed.y = *reinterpret_cast<uint32_t*>(&p23);
            packed.z = *reinterpret_cast<uint32_t*>(&p45);
            packed.w = *reinterpret_cast<uint32_t*>(&p67);
            uint32_t byte = (uint32_t)pr_r * 128u + (uint32_t)(pr_seg * 8) * 2u;
            *reinterpret_cast<uint4*>(al + ps_off + sw128(byte)) = packed;
            rs_reg += pr[0] + pr[1] + pr[2] + pr[3] + pr[4] + pr[5] + pr[6] + pr[7];
        }

        // 2. Hs(gc) landed (keep 1 group in flight), group barrier
        cp_wait_1();
        bar_named(barid, 512);

        // 3. MMA(gc): warp 32x32 tile
#pragma unroll
        for (int ks = 0; ks < 4; ks++) {
            const uint32_t kb = (uint32_t)(ks * 16 + (lane >> 4) * 8) * 2u;
            uint32_t a[2][4];
#pragma unroll
            for (int mt = 0; mt < 2; mt++) {
                uint32_t addr = base + ps_off +
                    sw128((uint32_t)(mrow0 + mt * 16 + (lane & 15)) * 128u + kb);
                ldm_x4(a[mt][0], a[mt][1], a[mt][2], a[mt][3], addr);
            }
            uint32_t b[4][2];
#pragma unroll
            for (int np = 0; np < 2; np++) {
                uint32_t r0, r1, r2, r3;
                uint32_t addr = base + hs_off +
                    sw128((uint32_t)(ncol0 + np * 16 + (lane & 15)) * 128u + kb);
                ldm_x4(r0, r1, r2, r3, addr);
                b[2 * np][0] = r0; b[2 * np][1] = r2;
                b[2 * np + 1][0] = r1; b[2 * np + 1][1] = r3;
            }
#pragma unroll
            for (int mt = 0; mt < 2; mt++)
#pragma unroll
                for (int nt = 0; nt < 4; nt++)
                    mma_16816(acc[mt][nt], a[mt], b[nt]);
        }

        // 4. group barrier: P + Hs(gc) free
        bar_named(barid, 512);

        // 5. prefetch Hs(gc+4) into the freed buffer; M(gc+2) into regs
        if (i + 2 < NCHUNK / 2) {
            const int gcn = gc + 4;
#pragma unroll
            for (int q = 0; q < 4; q++) {
                int id = gtid + q * 512;
                int n = id >> 3, kq = id & 7;
                cp_async16(base + HS_OFF(par, i & 1) + sw128((uint32_t)n * 128u + (uint32_t)kq * 16u),
                           g_HT + (size_t)n * NNODES + gcn * BK + kq * 8);
            }
        }
        cp_commit();   // unconditional: keeps wait_group accounting uniform
        if (i + 1 < NCHUNK / 2) {
            mcur0 = *reinterpret_cast<const float4*>(Mrow + (gc + 2) * BK);
            mcur1 = *reinterpret_cast<const float4*>(Mrow + (gc + 2) * BK + 4);
        }
    }

    // rowsum: 8 consecutive lanes share a row
    rs_reg += __shfl_xor_sync(0xffffffffu, rs_reg, 1);
    rs_reg += __shfl_xor_sync(0xffffffffu, rs_reg, 2);
    rs_reg += __shfl_xor_sync(0xffffffffu, rs_reg, 4);
    if ((gtid & 7) == 0)
        *(float*)(al + RS_OFF + par * 256 + pr_r * 4) = rs_reg;

    __syncthreads();

    // group 1 stores partial acc to SMEM (padded pitch for conflict-free)
    if (par == 1) {
        float* accs = (float*)(al + ACC_OFF);
#pragma unroll
        for (int mt = 0; mt < 2; mt++)
#pragma unroll
            for (int half = 0; half < 2; half++) {
                const int rl = mrow0 + mt * 16 + (lane >> 2) + half * 8;
#pragma unroll
                for (int nt = 0; nt < 4; nt++) {
                    const int col = ncol0 + nt * 8 + (lane & 3) * 2;
                    *reinterpret_cast<float2*>(accs + rl * ACC_PITCH + col) =
                        make_float2(acc[mt][nt][half * 2], acc[mt][nt][half * 2 + 1]);
                }
            }
    }
    __syncthreads();

    // group 0: combine + epilogue
    if (par == 0) {
        const float* accs = (const float*)(al + ACC_OFF);
        const float* rs0 = (const float*)(al + RS_OFF);
        const float* rs1 = (const float*)(al + RS_OFF + 256);
#pragma unroll
        for (int mt = 0; mt < 2; mt++) {
#pragma unroll
            for (int half = 0; half < 2; half++) {
                const int rl = mrow0 + mt * 16 + (lane >> 2) + half * 8;
                const int row = row0 + rl;
                const float rs = rs0[rl] + rs1[rl];
                const bool nb = !(rs > 0.f);
                const float inv = nb ? 0.f : 1.f / rs;
#pragma unroll
                for (int nt = 0; nt < 4; nt++) {
                    const int col = ncol0 + nt * 8 + (lane & 3) * 2;
                    float2 other = *reinterpret_cast<const float2*>(accs + rl * ACC_PITCH + col);
                    float u0 = (acc[mt][nt][2 * half]     + other.x) * inv;
                    float u1 = (acc[mt][nt][2 * half + 1] + other.y) * inv;
                    if (nb) {
                        u0 = g_H[(size_t)row * FOUT + col];
                        u1 = g_H[(size_t)row * FOUT + col + 1];
                    }
                    float2 z;
                    z.x = 1.f / (1.f + __expf(-u0));
                    z.y = 1.f / (1.f + __expf(-u1));
                    *reinterpret_cast<float2*>(out + (size_t)row * FOUT + col) = z;
                }
            }
        }
    }
}

// ---------------- launch ----------------
extern "C" void kernel_launch(void* const* d_in, const int* in_sizes, int n_in,
                              void* d_out, int out_size) {
    const float *X = nullptr, *M = nullptr, *W = nullptr, *AW = nullptr;
    for (int i = 0; i < n_in; i++) {
        switch (in_sizes[i]) {
            case NNODES * FIN:    X  = (const float*)d_in[i]; break;
            case NNODES * NNODES: M  = (const float*)d_in[i]; break;
            case FOUT * FIN:      W  = (const float*)d_in[i]; break;
            case 2 * FOUT:        AW = (const float*)d_in[i]; break;
            default: break;
        }
    }
    float* out = (float*)d_out;

    cudaFuncSetAttribute(gemm_H_tf32_kernel,
                         cudaFuncAttributeMaxDynamicSharedMemorySize, GEMM_SMEM);
    cudaFuncSetAttribute(attn_mma_kernel,
                         cudaFuncAttributeMaxDynamicSharedMemorySize, SMEM_DYN);

    dim3 gH(NNODES / 128, FOUT / 64);
    gemm_H_tf32_kernel<<<gH, 256, GEMM_SMEM>>>(X, W);
    st_kernel<<<NNODES / 8, 256>>>(AW);
    attn_mma_kernel<<<NNODES / BM, ATTN_THREADS, SMEM_DYN>>>(M, out);
}

// round 12
// speedup vs baseline: 1.0014x; 1.0014x over previous
// ============================================================================
// R12: R6 structure (best known: 254 us) with BK=128 (64 chunks instead of
// 128) to halve per-chunk fixed overhead (~1000 cyc/chunk measured above the
// smem-crossbar floor). 256B-row tiles use swizzle b ^ ((b>>4)&0x70).
// Prediction: total 254 -> ~220-235 us, rel_err ~4.4e-5.
// ============================================================================
#include <cuda_runtime.h>
#include <cuda_bf16.h>
#include <math_constants.h>
#include <cstdint>

#define NNODES 8192
#define FIN    512
#define FOUT   256
#define NEG_SLOPE 0.2f

#define BM 64
#define BK 128
#define NCHUNK (NNODES / BK)     // 64
#define ATTN_THREADS 1024

// ---------------- device scratch ----------------
__device__ float         g_H [NNODES * FOUT];
__device__ __nv_bfloat16 g_HT[FOUT * NNODES];
__device__ float         g_s [NNODES];
__device__ float         g_t [NNODES];

// ---------------- helpers (base PTX, sm_80-compatible) ----------------
static __device__ __forceinline__ uint32_t smem_u32(const void* p) {
    uint32_t a;
    asm("{ .reg .u64 t; cvta.to.shared.u64 t, %1; cvt.u32.u64 %0, t; }" : "=r"(a) : "l"(p));
    return a;
}
static __device__ __forceinline__ void cp_async16(uint32_t dst, const void* src) {
    asm volatile("cp.async.cg.shared.global [%0], [%1], 16;" :: "r"(dst), "l"(src));
}
static __device__ __forceinline__ void cp_commit() {
    asm volatile("cp.async.commit_group;" ::: "memory");
}
static __device__ __forceinline__ void cp_wait_all() {
    asm volatile("cp.async.wait_group 0;" ::: "memory");
}
static __device__ __forceinline__ void ldm_x4(uint32_t& r0, uint32_t& r1,
                                              uint32_t& r2, uint32_t& r3, uint32_t addr) {
    asm volatile("ldmatrix.sync.aligned.m8n8.x4.shared.b16 {%0, %1, %2, %3}, [%4];"
                 : "=r"(r0), "=r"(r1), "=r"(r2), "=r"(r3) : "r"(addr));
}
static __device__ __forceinline__ void mma_16816(float* d, const uint32_t* a, const uint32_t* b) {
    asm volatile(
        "mma.sync.aligned.m16n8k16.row.col.f32.bf16.bf16.f32 "
        "{%0, %1, %2, %3}, {%4, %5, %6, %7}, {%8, %9}, {%0, %1, %2, %3};"
        : "+f"(d[0]), "+f"(d[1]), "+f"(d[2]), "+f"(d[3])
        : "r"(a[0]), "r"(a[1]), "r"(a[2]), "r"(a[3]), "r"(b[0]), "r"(b[1]));
}
static __device__ __forceinline__ void mma_tf32(float* d, const uint32_t* a, const uint32_t* b) {
    asm volatile(
        "mma.sync.aligned.m16n8k8.row.col.f32.tf32.tf32.f32 "
        "{%0, %1, %2, %3}, {%4, %5, %6, %7}, {%8, %9}, {%0, %1, %2, %3};"
        : "+f"(d[0]), "+f"(d[1]), "+f"(d[2]), "+f"(d[3])
        : "r"(a[0]), "r"(a[1]), "r"(a[2]), "r"(a[3]), "r"(b[0]), "r"(b[1]));
}
static __device__ __forceinline__ uint32_t f2tf32(float v) {
    uint32_t r;
    asm("cvt.rna.tf32.f32 %0, %1;" : "=r"(r) : "f"(v));
    return r;
}
static __device__ __forceinline__ uint32_t sw128(uint32_t b) { return b ^ ((b >> 3) & 0x70); }
// 256-byte-row swizzle: XOR bits[6:4] with bits[10:8] (= row & 7 for 256B pitch)
static __device__ __forceinline__ uint32_t sw256(uint32_t b) { return b ^ ((b >> 4) & 0x70); }

// ---------------- Kernel 1: H = X @ W^T via tf32 mma ----------------
#define GPITCH 36
#define XS_OFF0 0u
#define XS_OFF1 18432u
#define WS_OFF0 36864u
#define WS_OFF1 46080u
#define GEMM_SMEM 55296

__global__ void __launch_bounds__(256)
gemm_H_tf32_kernel(const float* __restrict__ X, const float* __restrict__ W) {
    extern __shared__ char gsm[];
    const uint32_t base = smem_u32(gsm);
    float* sm = (float*)gsm;

    const int tid = threadIdx.x;
    const int lane = tid & 31;
    const int wid = tid >> 5;
    const int wm = (wid & 3) * 32;
    const int wn = (wid >> 2) * 32;
    const int row0 = blockIdx.x * 128;
    const int col0 = blockIdx.y * 64;

    float acc[2][4][4];
#pragma unroll
    for (int mt = 0; mt < 2; mt++)
#pragma unroll
        for (int nt = 0; nt < 4; nt++)
#pragma unroll
            for (int e = 0; e < 4; e++) acc[mt][nt][e] = 0.f;

#pragma unroll
    for (int q = 0; q < 4; q++) {
        int id = tid + q * 256;
        int r = id >> 3, kq = id & 7;
        cp_async16(base + XS_OFF0 + (uint32_t)(r * GPITCH + kq * 4) * 4u,
                   X + (size_t)(row0 + r) * FIN + kq * 4);
    }
#pragma unroll
    for (int q = 0; q < 2; q++) {
        int id = tid + q * 256;
        int r = id >> 3, kq = id & 7;
        cp_async16(base + WS_OFF0 + (uint32_t)(r * GPITCH + kq * 4) * 4u,
                   W + (size_t)(col0 + r) * FIN + kq * 4);
    }
    cp_commit();

    const int a_r = lane >> 2;
    const int a_k = lane & 3;

#pragma unroll 1
    for (int kb = 0; kb < FIN / 32; kb++) {
        const int buf = kb & 1;
        const uint32_t xs = buf ? XS_OFF1 : XS_OFF0;
        const uint32_t ws = buf ? WS_OFF1 : WS_OFF0;
        cp_wait_all();
        __syncthreads();

        if (kb + 1 < FIN / 32) {
            const uint32_t xsn = buf ? XS_OFF0 : XS_OFF1;
            const uint32_t wsn = buf ? WS_OFF0 : WS_OFF1;
            const int k0n = (kb + 1) * 32;
#pragma unroll
            for (int q = 0; q < 4; q++) {
                int id = tid + q * 256;
                int r = id >> 3, kq = id & 7;
                cp_async16(base + xsn + (uint32_t)(r * GPITCH + kq * 4) * 4u,
                           X + (size_t)(row0 + r) * FIN + k0n + kq * 4);
            }
#pragma unroll
            for (int q = 0; q < 2; q++) {
                int id = tid + q * 256;
                int r = id >> 3, kq = id & 7;
                cp_async16(base + wsn + (uint32_t)(r * GPITCH + kq * 4) * 4u,
                           W + (size_t)(col0 + r) * FIN + k0n + kq * 4);
            }
            cp_commit();
        }

        const float* Xs = (const float*)((const char*)sm + xs);
        const float* Ws = (const float*)((const char*)sm + ws);
#pragma unroll
        for (int kk = 0; kk < 32; kk += 8) {
            uint32_t a[2][4];
#pragma unroll
            for (int mt = 0; mt < 2; mt++) {
                const int m = wm + mt * 16 + a_r;
                a[mt][0] = f2tf32(Xs[m * GPITCH + kk + a_k]);
                a[mt][1] = f2tf32(Xs[(m + 8) * GPITCH + kk + a_k]);
                a[mt][2] = f2tf32(Xs[m * GPITCH + kk + a_k + 4]);
                a[mt][3] = f2tf32(Xs[(m + 8) * GPITCH + kk + a_k + 4]);
            }
            uint32_t b[4][2];
#pragma unroll
            for (int nt = 0; nt < 4; nt++) {
                const int n = wn + nt * 8 + a_r;
                b[nt][0] = f2tf32(Ws[n * GPITCH + kk + a_k]);
                b[nt][1] = f2tf32(Ws[n * GPITCH + kk + a_k + 4]);
            }
#pragma unroll
            for (int mt = 0; mt < 2; mt++)
#pragma unroll
                for (int nt = 0; nt < 4; nt++)
                    mma_tf32(acc[mt][nt], a[mt], b[nt]);
        }
    }

#pragma unroll
    for (int mt = 0; mt < 2; mt++) {
#pragma unroll
        for (int nt = 0; nt < 4; nt++) {
#pragma unroll
            for (int half = 0; half < 2; half++) {
                const int row = row0 + wm + mt * 16 + (lane >> 2) + half * 8;
                const int col = col0 + wn + nt * 8 + (lane & 3) * 2;
                float v0 = acc[mt][nt][2 * half];
                float v1 = acc[mt][nt][2 * half + 1];
                *reinterpret_cast<float2*>(g_H + (size_t)row * FOUT + col) = make_float2(v0, v1);
                g_HT[(size_t)col * NNODES + row]       = __float2bfloat16(v0);
                g_HT[(size_t)(col + 1) * NNODES + row] = __float2bfloat16(v1);
            }
        }
    }
}

// ---------------- Kernel 2: s = H a_l, t = H a_r ----------------
__global__ void st_kernel(const float* __restrict__ attn_w) {
    const int lane = threadIdx.x & 31;
    const int warp = threadIdx.x >> 5;
    const int row = blockIdx.x * 8 + warp;
    float s = 0.f, t = 0.f;
#pragma unroll
    for (int o = lane; o < FOUT; o += 32) {
        float h = g_H[(size_t)row * FOUT + o];
        s += h * attn_w[o];
        t += h * attn_w[FOUT + o];
    }
#pragma unroll
    for (int off = 16; off; off >>= 1) {
        s += __shfl_down_sync(0xffffffffu, s, off);
        t += __shfl_down_sync(0xffffffffu, t, off);
    }
    if (lane == 0) { g_s[row] = s; g_t[row] = t; }
}

// ---------------- Kernel 3: pipelined flash attention, BK=128 ----------------
// SMEM (from 1024-aligned base):
//   P bufs: 64 rows x 256 B = 16 KB each at 0 / 16384
//   Hs bufs: 256 rows x 256 B = 64 KB each at 32768 / 98304
//   rowsum: 64 floats at 163840
#define PS_OFF0 0u
#define PS_OFF1 16384u
#define HS_OFF0 32768u
#define HS_OFF1 98304u
#define RS_OFF  163840u
#define SMEM_DYN 165120

__global__ void __launch_bounds__(ATTN_THREADS, 1)
attn_mma_kernel(const float* __restrict__ M, float* __restrict__ out) {
    extern __shared__ char dsm[];
    const uint32_t raw = smem_u32(dsm);
    const uint32_t base = (raw + 1023u) & ~1023u;
    char* al = dsm + (base - raw);

    const int tid  = threadIdx.x;
    const int lane = tid & 31;
    const int wid  = tid >> 5;
    const int row0 = blockIdx.x * BM;

    float* rowsum = (float*)(al + RS_OFF);

    // P-producer: row = tid/16, 8 cols at (tid%16)*8
    const int pr_r   = tid >> 4;
    const int pr_seg = tid & 15;
    const float si = g_s[row0 + pr_r];
    const float* Mrow = M + (size_t)(row0 + pr_r) * NNODES + pr_seg * 8;
    const float* Trow = g_t + pr_seg * 8;

    // warp MMA tile: 16 rows x 32 cols. 32 warps: 4 m-groups x 8 n-groups
    const int mrow0 = (wid & 3) * 16;
    const int ncol0 = (wid >> 2) * 32;

    float acc[4][4];
#pragma unroll
    for (int nt = 0; nt < 4; nt++)
#pragma unroll
        for (int e = 0; e < 4; e++) acc[nt][e] = 0.f;

    float rs_reg = 0.f;

    // ---- prologue: Hs(0) (4096 uint4, 4/thread) ----
#pragma unroll
    for (int q = 0; q < 4; q++) {
        int id = tid + q * ATTN_THREADS;
        int n = id >> 4, kq = id & 15;
        cp_async16(base + HS_OFF0 + sw256((uint32_t)n * 256u + (uint32_t)kq * 16u),
                   g_HT + (size_t)n * NNODES + kq * 8);
    }
    cp_commit();

    // P(0) synchronous: 8 values/thread
    {
        float pr[8];
#pragma unroll
        for (int h = 0; h < 2; h++) {
            const float4 m4 = *reinterpret_cast<const float4*>(Mrow + h * 4);
            const float4 t4 = *reinterpret_cast<const float4*>(Trow + h * 4);
#pragma unroll
            for (int e = 0; e < 4; e++) {
                float m = (&m4.x)[e];
                float v = si + (&t4.x)[e];
                float lr = fmaxf(v, NEG_SLOPE * v);
                float pv = (m > 0.f) ? __expf(m * lr) : 0.f;
                pr[h * 4 + e] = __bfloat162float(__float2bfloat16(pv));
            }
        }
        uint4 packed;
        __nv_bfloat162 p01 = __floats2bfloat162_rn(pr[0], pr[1]);
        __nv_bfloat162 p23 = __floats2bfloat162_rn(pr[2], pr[3]);
        __nv_bfloat162 p45 = __floats2bfloat162_rn(pr[4], pr[5]);
        __nv_bfloat162 p67 = __floats2bfloat162_rn(pr[6], pr[7]);
        packed.x = *reinterpret_cast<uint32_t*>(&p01);
        packed.y = *reinterpret_cast<uint32_t*>(&p23);
        packed.z = *reinterpret_cast<uint32_t*>(&p45);
        packed.w = *reinterpret_cast<uint32_t*>(&p67);
        uint32_t byte = (uint32_t)pr_r * 256u + (uint32_t)pr_seg * 16u;
        *reinterpret_cast<uint4*>(al + PS_OFF0 + sw256(byte)) = packed;
        rs_reg += pr[0] + pr[1] + pr[2] + pr[3] + pr[4] + pr[5] + pr[6] + pr[7];
    }

    // M(1) prefetch
    float4 mcur0 = *reinterpret_cast<const float4*>(Mrow + BK);
    float4 mcur1 = *reinterpret_cast<const float4*>(Mrow + BK + 4);

#pragma unroll 1
    for (int c = 0; c < NCHUNK; ++c) {
        const int buf = c & 1;
        const uint32_t ps_off = buf ? PS_OFF1 : PS_OFF0;
        const uint32_t hs_off = buf ? HS_OFF1 : HS_OFF0;

        cp_wait_all();
        __syncthreads();   // Hs(c) + P(c) visible; prior-chunk buffer readers done

        const int cn = c + 1;
        if (cn < NCHUNK) {
            const uint32_t hs_nxt = buf ? HS_OFF0 : HS_OFF1;
            const uint32_t ps_nxt = buf ? PS_OFF0 : PS_OFF1;
            // prefetch Hs(c+1)
#pragma unroll
            for (int q = 0; q < 4; q++) {
                int id = tid + q * ATTN_THREADS;
                int n = id >> 4, kq = id & 15;
                cp_async16(base + hs_nxt + sw256((uint32_t)n * 256u + (uint32_t)kq * 16u),
                           g_HT + (size_t)n * NNODES + cn * BK + kq * 8);
            }
            cp_commit();

            // prefetch M(c+2)
            float4 mn0, mn1;
            if (c + 2 < NCHUNK) {
                mn0 = *reinterpret_cast<const float4*>(Mrow + (c + 2) * BK);
                mn1 = *reinterpret_cast<const float4*>(Mrow + (c + 2) * BK + 4);
            }

            // compute P(c+1) from mcur into ps_nxt
            {
                const float* tp = Trow + cn * BK;
                const float4 t40 = *reinterpret_cast<const float4*>(tp);
                const float4 t41 = *reinterpret_cast<const float4*>(tp + 4);
                float pr[8];
#pragma unroll
                for (int e = 0; e < 4; e++) {
                    float m = (&mcur0.x)[e];
                    float v = si + (&t40.x)[e];
                    float lr = fmaxf(v, NEG_SLOPE * v);
                    float pv = (m > 0.f) ? __expf(m * lr) : 0.f;
                    pr[e] = __bfloat162float(__float2bfloat16(pv));
                }
#pragma unroll
                for (int e = 0; e < 4; e++) {
                    float m = (&mcur1.x)[e];
                    float v = si + (&t41.x)[e];
                    float lr = fmaxf(v, NEG_SLOPE * v);
                    float pv = (m > 0.f) ? __expf(m * lr) : 0.f;
                    pr[4 + e] = __bfloat162float(__float2bfloat16(pv));
                }
                uint4 packed;
                __nv_bfloat162 p01 = __floats2bfloat162_rn(pr[0], pr[1]);
                __nv_bfloat162 p23 = __floats2bfloat162_rn(pr[2], pr[3]);
                __nv_bfloat162 p45 = __floats2bfloat162_rn(pr[4], pr[5]);
                __nv_bfloat162 p67 = __floats2bfloat162_rn(pr[6], pr[7]);
                packed.x = *reinterpret_cast<uint32_t*>(&p01);
                packed.y = *reinterpret_cast<uint32_t*>(&p23);
                packed.z = *reinterpret_cast<uint32_t*>(&p45);
                packed.w = *reinterpret_cast<uint32_t*>(&p67);
                uint32_t byte = (uint32_t)pr_r * 256u + (uint32_t)pr_seg * 16u;
                *reinterpret_cast<uint4*>(al + ps_nxt + sw256(byte)) = packed;
                rs_reg += pr[0] + pr[1] + pr[2] + pr[3] + pr[4] + pr[5] + pr[6] + pr[7];
            }
            mcur0 = mn0; mcur1 = mn1;
        }

        // MMA(c): 8 ksteps, warp tile 16x32
#pragma unroll
        for (int ks = 0; ks < 8; ks++) {
            const uint32_t kb = (uint32_t)(ks * 16 + (lane >> 4) * 8) * 2u;
            uint32_t a[4];
            {
                uint32_t addr = base + ps_off +
                    sw256((uint32_t)(mrow0 + (lane & 15)) * 256u + kb);
                ldm_x4(a[0], a[1], a[2], a[3], addr);
            }
            uint32_t b[4][2];
#pragma unroll
            for (int np = 0; np < 2; np++) {
                uint32_t r0, r1, r2, r3;
                uint32_t addr = base + hs_off +
                    sw256((uint32_t)(ncol0 + np * 16 + (lane & 15)) * 256u + kb);
                ldm_x4(r0, r1, r2, r3, addr);
                b[2 * np][0] = r0; b[2 * np][1] = r2;
                b[2 * np + 1][0] = r1; b[2 * np + 1][1] = r3;
            }
#pragma unroll
            for (int nt = 0; nt < 4; nt++)
                mma_16816(acc[nt], a, b[nt]);
        }
    }

    // rowsum: 16 consecutive lanes share a row
    rs_reg += __shfl_xor_sync(0xffffffffu, rs_reg, 1);
    rs_reg += __shfl_xor_sync(0xffffffffu, rs_reg, 2);
    rs_reg += __shfl_xor_sync(0xffffffffu, rs_reg, 4);
    rs_reg += __shfl_xor_sync(0xffffffffu, rs_reg, 8);
    if ((tid & 15) == 0) rowsum[pr_r] = rs_reg;
    __syncthreads();

    // epilogue: warp tile 16x32
#pragma unroll
    for (int half = 0; half < 2; half++) {
        const int rl = mrow0 + (lane >> 2) + half * 8;
        const int row = row0 + rl;
        const float rs = rowsum[rl];
        const bool nb = !(rs > 0.f);
        const float inv = nb ? 0.f : 1.f / rs;
#pragma unroll
        for (int nt = 0; nt < 4; nt++) {
            const int col = ncol0 + nt * 8 + (lane & 3) * 2;
            float u0 = acc[nt][2 * half]     * inv;
            float u1 = acc[nt][2 * half + 1] * inv;
            if (nb) {
                u0 = g_H[(size_t)row * FOUT + col];
                u1 = g_H[(size_t)row * FOUT + col + 1];
            }
            float2 z;
            z.x = 1.f / (1.f + __expf(-u0));
            z.y = 1.f / (1.f + __expf(-u1));
            *reinterpret_cast<float2*>(out + (size_t)row * FOUT + col) = z;
        }
    }
}

// ---------------- launch ----------------
extern "C" void kernel_launch(void* const* d_in, const int* in_sizes, int n_in,
                              void* d_out, int out_size) {
    const float *X = nullptr, *M = nullptr, *W = nullptr, *AW = nullptr;
    for (int i = 0; i < n_in; i++) {
        switch (in_sizes[i]) {
            case NNODES * FIN:    X  = (const float*)d_in[i]; break;
            case NNODES * NNODES: M  = (const float*)d_in[i]; break;
            case FOUT * FIN:      W  = (const float*)d_in[i]; break;
            case 2 * FOUT:        AW = (const float*)d_in[i]; break;
            default: break;
        }
    }
    float* out = (float*)d_out;

    cudaFuncSetAttribute(gemm_H_tf32_kernel,
                         cudaFuncAttributeMaxDynamicSharedMemorySize, GEMM_SMEM);
    cudaFuncSetAttribute(attn_mma_kernel,
                         cudaFuncAttributeMaxDynamicSharedMemorySize, SMEM_DYN);

    dim3 gH(NNODES / 128, FOUT / 64);
    gemm_H_tf32_kernel<<<gH, 256, GEMM_SMEM>>>(X, W);
    st_kernel<<<NNODES / 8, 256>>>(AW);
    attn_mma_kernel<<<NNODES / BM, ATTN_THREADS, SMEM_DYN>>>(M, out);
}

// round 13
// speedup vs baseline: 1.1442x; 1.1426x over previous
// ============================================================================
// R13: R6 base (best: 254us). Change: eliminate the transposed g_HT scatter.
// H[node][fout] is already K-major for the attention B operand, so gemm_H
// stores row-major bf16 g_Hb (coalesced) and attn loads B tiles as contiguous
// H rows (512B pitch, swizzle b^((b>>5)&0x70)) with ldmatrix.x4.trans.
// Prediction: gemm 31 -> ~20us, total 254 -> ~238-245us, rel_err ~4.4e-5.
// ============================================================================
#include <cuda_runtime.h>
#include <cuda_bf16.h>
#include <math_constants.h>
#include <cstdint>

#define NNODES 8192
#define FIN    512
#define FOUT   256
#define NEG_SLOPE 0.2f

#define BM 64
#define BK 64
#define NCHUNK (NNODES / BK)     // 128
#define ATTN_THREADS 1024

// ---------------- device scratch ----------------
__device__ float         g_H [NNODES * FOUT];   // fp32 row-major (epilogue/st)
__device__ __nv_bfloat16 g_Hb[NNODES * FOUT];   // bf16 row-major (attn B operand)
__device__ float         g_s [NNODES];
__device__ float         g_t [NNODES];

// ---------------- helpers (base PTX, sm_80-compatible) ----------------
static __device__ __forceinline__ uint32_t smem_u32(const void* p) {
    uint32_t a;
    asm("{ .reg .u64 t; cvta.to.shared.u64 t, %1; cvt.u32.u64 %0, t; }" : "=r"(a) : "l"(p));
    return a;
}
static __device__ __forceinline__ void cp_async16(uint32_t dst, const void* src) {
    asm volatile("cp.async.cg.shared.global [%0], [%1], 16;" :: "r"(dst), "l"(src));
}
static __device__ __forceinline__ void cp_commit() {
    asm volatile("cp.async.commit_group;" ::: "memory");
}
static __device__ __forceinline__ void cp_wait_all() {
    asm volatile("cp.async.wait_group 0;" ::: "memory");
}
static __device__ __forceinline__ void ldm_x4(uint32_t& r0, uint32_t& r1,
                                              uint32_t& r2, uint32_t& r3, uint32_t addr) {
    asm volatile("ldmatrix.sync.aligned.m8n8.x4.shared.b16 {%0, %1, %2, %3}, [%4];"
                 : "=r"(r0), "=r"(r1), "=r"(r2), "=r"(r3) : "r"(addr));
}
static __device__ __forceinline__ void ldm_x4_trans(uint32_t& r0, uint32_t& r1,
                                                    uint32_t& r2, uint32_t& r3, uint32_t addr) {
    asm volatile("ldmatrix.sync.aligned.m8n8.x4.trans.shared.b16 {%0, %1, %2, %3}, [%4];"
                 : "=r"(r0), "=r"(r1), "=r"(r2), "=r"(r3) : "r"(addr));
}
static __device__ __forceinline__ void mma_16816(float* d, const uint32_t* a, const uint32_t* b) {
    asm volatile(
        "mma.sync.aligned.m16n8k16.row.col.f32.bf16.bf16.f32 "
        "{%0, %1, %2, %3}, {%4, %5, %6, %7}, {%8, %9}, {%0, %1, %2, %3};"
        : "+f"(d[0]), "+f"(d[1]), "+f"(d[2]), "+f"(d[3])
        : "r"(a[0]), "r"(a[1]), "r"(a[2]), "r"(a[3]), "r"(b[0]), "r"(b[1]));
}
static __device__ __forceinline__ void mma_tf32(float* d, const uint32_t* a, const uint32_t* b) {
    asm volatile(
        "mma.sync.aligned.m16n8k8.row.col.f32.tf32.tf32.f32 "
        "{%0, %1, %2, %3}, {%4, %5, %6, %7}, {%8, %9}, {%0, %1, %2, %3};"
        : "+f"(d[0]), "+f"(d[1]), "+f"(d[2]), "+f"(d[3])
        : "r"(a[0]), "r"(a[1]), "r"(a[2]), "r"(a[3]), "r"(b[0]), "r"(b[1]));
}
static __device__ __forceinline__ uint32_t f2tf32(float v) {
    uint32_t r;
    asm("cvt.rna.tf32.f32 %0, %1;" : "=r"(r) : "f"(v));
    return r;
}
static __device__ __forceinline__ uint32_t sw128(uint32_t b) { return b ^ ((b >> 3) & 0x70); }
// 512-byte-row swizzle: XOR bits[6:4] with bits[11:9] (= row & 7 for 512B pitch)
static __device__ __forceinline__ uint32_t sw512(uint32_t b) { return b ^ ((b >> 5) & 0x70); }

// ---------------- Kernel 1: H = X @ W^T via tf32 mma ----------------
#define GPITCH 36
#define XS_OFF0 0u
#define XS_OFF1 18432u
#define WS_OFF0 36864u
#define WS_OFF1 46080u
#define GEMM_SMEM 55296

__global__ void __launch_bounds__(256)
gemm_H_tf32_kernel(const float* __restrict__ X, const float* __restrict__ W) {
    extern __shared__ char gsm[];
    const uint32_t base = smem_u32(gsm);
    float* sm = (float*)gsm;

    const int tid = threadIdx.x;
    const int lane = tid & 31;
    const int wid = tid >> 5;
    const int wm = (wid & 3) * 32;
    const int wn = (wid >> 2) * 32;
    const int row0 = blockIdx.x * 128;
    const int col0 = blockIdx.y * 64;

    float acc[2][4][4];
#pragma unroll
    for (int mt = 0; mt < 2; mt++)
#pragma unroll
        for (int nt = 0; nt < 4; nt++)
#pragma unroll
            for (int e = 0; e < 4; e++) acc[mt][nt][e] = 0.f;

#pragma unroll
    for (int q = 0; q < 4; q++) {
        int id = tid + q * 256;
        int r = id >> 3, kq = id & 7;
        cp_async16(base + XS_OFF0 + (uint32_t)(r * GPITCH + kq * 4) * 4u,
                   X + (size_t)(row0 + r) * FIN + kq * 4);
    }
#pragma unroll
    for (int q = 0; q < 2; q++) {
        int id = tid + q * 256;
        int r = id >> 3, kq = id & 7;
        cp_async16(base + WS_OFF0 + (uint32_t)(r * GPITCH + kq * 4) * 4u,
                   W + (size_t)(col0 + r) * FIN + kq * 4);
    }
    cp_commit();

    const int a_r = lane >> 2;
    const int a_k = lane & 3;

#pragma unroll 1
    for (int kb = 0; kb < FIN / 32; kb++) {
        const int buf = kb & 1;
        const uint32_t xs = buf ? XS_OFF1 : XS_OFF0;
        const uint32_t ws = buf ? WS_OFF1 : WS_OFF0;
        cp_wait_all();
        __syncthreads();

        if (kb + 1 < FIN / 32) {
            const uint32_t xsn = buf ? XS_OFF0 : XS_OFF1;
            const uint32_t wsn = buf ? WS_OFF0 : WS_OFF1;
            const int k0n = (kb + 1) * 32;
#pragma unroll
            for (int q = 0; q < 4; q++) {
                int id = tid + q * 256;
                int r = id >> 3, kq = id & 7;
                cp_async16(base + xsn + (uint32_t)(r * GPITCH + kq * 4) * 4u,
                           X + (size_t)(row0 + r) * FIN + k0n + kq * 4);
            }
#pragma unroll
            for (int q = 0; q < 2; q++) {
                int id = tid + q * 256;
                int r = id >> 3, kq = id & 7;
                cp_async16(base + wsn + (uint32_t)(r * GPITCH + kq * 4) * 4u,
                           W + (size_t)(col0 + r) * FIN + k0n + kq * 4);
            }
            cp_commit();
        }

        const float* Xs = (const float*)((const char*)sm + xs);
        const float* Ws = (const float*)((const char*)sm + ws);
#pragma unroll
        for (int kk = 0; kk < 32; kk += 8) {
            uint32_t a[2][4];
#pragma unroll
            for (int mt = 0; mt < 2; mt++) {
                const int m = wm + mt * 16 + a_r;
                a[mt][0] = f2tf32(Xs[m * GPITCH + kk + a_k]);
                a[mt][1] = f2tf32(Xs[(m + 8) * GPITCH + kk + a_k]);
                a[mt][2] = f2tf32(Xs[m * GPITCH + kk + a_k + 4]);
                a[mt][3] = f2tf32(Xs[(m + 8) * GPITCH + kk + a_k + 4]);
            }
            uint32_t b[4][2];
#pragma unroll
            for (int nt = 0; nt < 4; nt++) {
                const int n = wn + nt * 8 + a_r;
                b[nt][0] = f2tf32(Ws[n * GPITCH + kk + a_k]);
                b[nt][1] = f2tf32(Ws[n * GPITCH + kk + a_k + 4]);
            }
#pragma unroll
            for (int mt = 0; mt < 2; mt++)
#pragma unroll
                for (int nt = 0; nt < 4; nt++)
                    mma_tf32(acc[mt][nt], a[mt], b[nt]);
        }
    }

    // epilogue: H fp32 + Hb bf16, both row-major (coalesced)
#pragma unroll
    for (int mt = 0; mt < 2; mt++) {
#pragma unroll
        for (int nt = 0; nt < 4; nt++) {
#pragma unroll
            for (int half = 0; half < 2; half++) {
                const int row = row0 + wm + mt * 16 + (lane >> 2) + half * 8;
                const int col = col0 + wn + nt * 8 + (lane & 3) * 2;
                float v0 = acc[mt][nt][2 * half];
                float v1 = acc[mt][nt][2 * half + 1];
                *reinterpret_cast<float2*>(g_H + (size_t)row * FOUT + col) = make_float2(v0, v1);
                __nv_bfloat162 hb = __floats2bfloat162_rn(v0, v1);
                *reinterpret_cast<__nv_bfloat162*>(g_Hb + (size_t)row * FOUT + col) = hb;
            }
        }
    }
}

// ---------------- Kernel 2: s = H a_l, t = H a_r ----------------
__global__ void st_kernel(const float* __restrict__ attn_w) {
    const int lane = threadIdx.x & 31;
    const int warp = threadIdx.x >> 5;
    const int row = blockIdx.x * 8 + warp;
    float s = 0.f, t = 0.f;
#pragma unroll
    for (int o = lane; o < FOUT; o += 32) {
        float h = g_H[(size_t)row * FOUT + o];
        s += h * attn_w[o];
        t += h * attn_w[FOUT + o];
    }
#pragma unroll
    for (int off = 16; off; off >>= 1) {
        s += __shfl_down_sync(0xffffffffu, s, off);
        t += __shfl_down_sync(0xffffffffu, t, off);
    }
    if (lane == 0) { g_s[row] = s; g_t[row] = t; }
}

// ---------------- Kernel 3: pipelined flash attention (R6 structure) ----------------
// SMEM: P bufs 8KB x2 at 0/8192; Hs bufs (64 k-rows x 512B) 32KB x2 at 16384/49152;
// rowsum at 81920.
#define PS_OFF0 0u
#define PS_OFF1 8192u
#define HS_OFF0 16384u
#define HS_OFF1 49152u
#define RS_OFF  81920u
#define SMEM_DYN 83456

__global__ void __launch_bounds__(ATTN_THREADS, 1)
attn_mma_kernel(const float* __restrict__ M, float* __restrict__ out) {
    extern __shared__ char dsm[];
    const uint32_t raw = smem_u32(dsm);
    const uint32_t base = (raw + 1023u) & ~1023u;
    char* al = dsm + (base - raw);

    const int tid  = threadIdx.x;
    const int lane = tid & 31;
    const int wid  = tid >> 5;
    const int row0 = blockIdx.x * BM;

    float* rowsum = (float*)(al + RS_OFF);

    // P-producer: row = tid/16, 4 cols at (tid%16)*4
    const int pr_r   = tid >> 4;
    const int pr_seg = tid & 15;
    const float si = g_s[row0 + pr_r];
    const float* Mrow = M + (size_t)(row0 + pr_r) * NNODES + pr_seg * 4;
    const float* Trow = g_t + pr_seg * 4;

    // warp MMA tile: 16 rows x 32 cols. 32 warps: 4 m-groups x 8 n-groups
    const int mrow0 = (wid & 3) * 16;
    const int ncol0 = (wid >> 2) * 32;

    float acc[4][4];
#pragma unroll
    for (int nt = 0; nt < 4; nt++)
#pragma unroll
        for (int e = 0; e < 4; e++) acc[nt][e] = 0.f;

    float rs_reg = 0.f;

    // B-tile ldmatrix.trans lane addressing (row-major [k][n], 512B pitch):
    // row = k16 + ((lane>>3)&1)*8 + (lane&7), col-base += ((lane>>4)&1)*8
    const uint32_t bt_row = (uint32_t)(((lane >> 3) & 1) * 8 + (lane & 7));
    const uint32_t bt_nc  = (uint32_t)(((lane >> 4) & 1) * 8);

    // ---- prologue: Hs(0) — 2048 uint4 (64 rows x 32 chunks), 2/thread ----
#pragma unroll
    for (int q = 0; q < 2; q++) {
        int id = tid + q * ATTN_THREADS;
        int k = id >> 5, n16 = id & 31;
        cp_async16(base + HS_OFF0 + sw512((uint32_t)k * 512u + (uint32_t)n16 * 16u),
                   g_Hb + (size_t)k * FOUT + n16 * 8);
    }
    cp_commit();

    // P(0) synchronous
    {
        const float4 m4 = *reinterpret_cast<const float4*>(Mrow);
        const float4 t4 = *reinterpret_cast<const float4*>(Trow);
        float pr[4];
#pragma unroll
        for (int e = 0; e < 4; e++) {
            float m = (&m4.x)[e];
            float v = si + (&t4.x)[e];
            float lr = fmaxf(v, NEG_SLOPE * v);
            float pv = (m > 0.f) ? __expf(m * lr) : 0.f;
            pr[e] = __bfloat162float(__float2bfloat16(pv));
        }
        __nv_bfloat162 p01 = __floats2bfloat162_rn(pr[0], pr[1]);
        __nv_bfloat162 p23 = __floats2bfloat162_rn(pr[2], pr[3]);
        uint2 packed;
        packed.x = *reinterpret_cast<uint32_t*>(&p01);
        packed.y = *reinterpret_cast<uint32_t*>(&p23);
        uint32_t byte = (uint32_t)pr_r * 128u + (uint32_t)(pr_seg * 4) * 2u;
        *reinterpret_cast<uint2*>(al + PS_OFF0 + sw128(byte)) = packed;
        rs_reg += pr[0] + pr[1] + pr[2] + pr[3];
    }

    // M(1) prefetch
    float4 mcur = *reinterpret_cast<const float4*>(Mrow + BK);

#pragma unroll 1
    for (int c = 0; c < NCHUNK; ++c) {
        const int buf = c & 1;
        const uint32_t ps_off = buf ? PS_OFF1 : PS_OFF0;
        const uint32_t hs_off = buf ? HS_OFF1 : HS_OFF0;

        cp_wait_all();
        __syncthreads();

        const int cn = c + 1;
        if (cn < NCHUNK) {
            const uint32_t hs_nxt = buf ? HS_OFF0 : HS_OFF1;
            const uint32_t ps_nxt = buf ? PS_OFF0 : PS_OFF1;
#pragma unroll
            for (int q = 0; q < 2; q++) {
                int id = tid + q * ATTN_THREADS;
                int k = id >> 5, n16 = id & 31;
                cp_async16(base + hs_nxt + sw512((uint32_t)k * 512u + (uint32_t)n16 * 16u),
                           g_Hb + (size_t)(cn * BK + k) * FOUT + n16 * 8);
            }
            cp_commit();

            float4 mnext;
            if (c + 2 < NCHUNK)
                mnext = *reinterpret_cast<const float4*>(Mrow + (c + 2) * BK);

            // P(c+1)
            {
                const float4 t4 = *reinterpret_cast<const float4*>(Trow + cn * BK);
                float pr[4];
#pragma unroll
                for (int e = 0; e < 4; e++) {
                    float m = (&mcur.x)[e];
                    float v = si + (&t4.x)[e];
                    float lr = fmaxf(v, NEG_SLOPE * v);
                    float pv = (m > 0.f) ? __expf(m * lr) : 0.f;
                    pr[e] = __bfloat162float(__float2bfloat16(pv));
                }
                __nv_bfloat162 p01 = __floats2bfloat162_rn(pr[0], pr[1]);
                __nv_bfloat162 p23 = __floats2bfloat162_rn(pr[2], pr[3]);
                uint2 packed;
                packed.x = *reinterpret_cast<uint32_t*>(&p01);
                packed.y = *reinterpret_cast<uint32_t*>(&p23);
                uint32_t byte = (uint32_t)pr_r * 128u + (uint32_t)(pr_seg * 4) * 2u;
                *reinterpret_cast<uint2*>(al + ps_nxt + sw128(byte)) = packed;
                rs_reg += pr[0] + pr[1] + pr[2] + pr[3];
            }
            mcur = mnext;
        }

        // MMA(c): per warp 16x32 tile, 4 k16 steps
#pragma unroll
        for (int ks = 0; ks < 4; ks++) {
            const uint32_t k16 = (uint32_t)(ks * 16);
            // A fragment (P, K-major rows, 128B pitch, non-trans)
            uint32_t a[4];
            {
                const uint32_t kb = (k16 + (uint32_t)((lane >> 4) * 8)) * 2u;
                uint32_t addr = base + ps_off +
                    sw128((uint32_t)(mrow0 + (lane & 15)) * 128u + kb);
                ldm_x4(a[0], a[1], a[2], a[3], addr);
            }
            // B fragments via ldmatrix.x4.trans: each covers 16 n-cols
            uint32_t b[4][2];
#pragma unroll
            for (int half = 0; half < 2; half++) {
                uint32_t r0, r1, r2, r3;
                uint32_t row = k16 + bt_row;
                uint32_t nc  = (uint32_t)(ncol0 + half * 16) + bt_nc;
                uint32_t addr = base + hs_off + sw512(row * 512u + nc * 2u);
                ldm_x4_trans(r0, r1, r2, r3, addr);
                b[2 * half][0] = r0;     b[2 * half][1] = r1;      // n8 group 0
                b[2 * half + 1][0] = r2; b[2 * half + 1][1] = r3;  // n8 group 1
            }
#pragma unroll
            for (int nt = 0; nt < 4; nt++)
                mma_16816(acc[nt], a, b[nt]);
        }
    }

    // rowsum: 16 consecutive lanes share a row
    rs_reg += __shfl_xor_sync(0xffffffffu, rs_reg, 1);
    rs_reg += __shfl_xor_sync(0xffffffffu, rs_reg, 2);
    rs_reg += __shfl_xor_sync(0xffffffffu, rs_reg, 4);
    rs_reg += __shfl_xor_sync(0xffffffffu, rs_reg, 8);
    if ((tid & 15) == 0) rowsum[pr_r] = rs_reg;
    __syncthreads();

    // epilogue: warp tile 16x32
#pragma unroll
    for (int half = 0; half < 2; half++) {
        const int rl = mrow0 + (lane >> 2) + half * 8;
        const int row = row0 + rl;
        const float rs = rowsum[rl];
        const bool nb = !(rs > 0.f);
        const float inv = nb ? 0.f : 1.f / rs;
#pragma unroll
        for (int nt = 0; nt < 4; nt++) {
            const int col = ncol0 + nt * 8 + (lane & 3) * 2;
            float u0 = acc[nt][2 * half]     * inv;
            float u1 = acc[nt][2 * half + 1] * inv;
            if (nb) {
                u0 = g_H[(size_t)row * FOUT + col];
                u1 = g_H[(size_t)row * FOUT + col + 1];
            }
            float2 z;
            z.x = 1.f / (1.f + __expf(-u0));
            z.y = 1.f / (1.f + __expf(-u1));
            *reinterpret_cast<float2*>(out + (size_t)row * FOUT + col) = z;
        }
    }
}

// ---------------- launch ----------------
extern "C" void kernel_launch(void* const* d_in, const int* in_sizes, int n_in,
                              void* d_out, int out_size) {
    const float *X = nullptr, *M = nullptr, *W = nullptr, *AW = nullptr;
    for (int i = 0; i < n_in; i++) {
        switch (in_sizes[i]) {
            case NNODES * FIN:    X  = (const float*)d_in[i]; break;
            case NNODES * NNODES: M  = (const float*)d_in[i]; break;
            case FOUT * FIN:      W  = (const float*)d_in[i]; break;
            case 2 * FOUT:        AW = (const float*)d_in[i]; break;
            default: break;
        }
    }
    float* out = (float*)d_out;

    cudaFuncSetAttribute(gemm_H_tf32_kernel,
                         cudaFuncAttributeMaxDynamicSharedMemorySize, GEMM_SMEM);
    cudaFuncSetAttribute(attn_mma_kernel,
                         cudaFuncAttributeMaxDynamicSharedMemorySize, SMEM_DYN);

    dim3 gH(NNODES / 128, FOUT / 64);
    gemm_H_tf32_kernel<<<gH, 256, GEMM_SMEM>>>(X, W);
    st_kernel<<<NNODES / 8, 256>>>(AW);
    attn_mma_kernel<<<NNODES / BM, ATTN_THREADS, SMEM_DYN>>>(M, out);
}